// round 4
// baseline (speedup 1.0000x reference)
#include <cuda_runtime.h>
#include <math.h>

#define NMAX   100000
#define ETOTMX 1700000
#define SCAN_CHUNK 1024
#define SCAN_NB_MAX 128

// ---------------- scratch (static device globals; no allocation) ----------
__device__ int   g_is64;
__device__ int   g_src[ETOTMX];
__device__ int   g_dst[ETOTMX];
__device__ int   g_csr[ETOTMX];
__device__ int   g_deg[NMAX];
__device__ int   g_cnt[NMAX];
__device__ int   g_rowptr[NMAX + 1];
__device__ int   g_bsum[SCAN_NB_MAX];
__device__ int   g_boff[SCAN_NB_MAX];
__device__ __align__(16) float g_h[NMAX * 64];
__device__ __align__(16) float g_agg[NMAX * 64];
__device__ float g_as[NMAX];
__device__ float g_ad[NMAX];

// ---------------- f32x2 packed fma helpers ---------------------------------
__device__ __forceinline__ void ffma2(unsigned long long& d,
                                      unsigned long long a,
                                      unsigned long long b) {
    asm("fma.rn.f32x2 %0, %1, %2, %0;" : "+l"(d) : "l"(a), "l"(b));
}
__device__ __forceinline__ unsigned long long pack2(float lo, float hi) {
    unsigned long long r;
    asm("mov.b64 %0, {%1, %2};" : "=l"(r) : "f"(lo), "f"(hi));
    return r;
}
__device__ __forceinline__ void unpack2(float& lo, float& hi, unsigned long long v) {
    asm("mov.b64 {%0, %1}, %2;" : "=f"(lo), "=f"(hi) : "l"(v));
}

// ---------------- dtype sniff: int64 vs int32 edge_index -------------------
__global__ void detect_kernel(const int* __restrict__ ei32) {
    if (threadIdx.x == 0) {
        int ok = 1;
        for (int i = 0; i < 256; i++)
            if (ei32[2 * i + 1] != 0) { ok = 0; break; }
        g_is64 = ok;
    }
}

// ---------------- graph build ---------------------------------------------
__global__ void zero_counts_kernel(int nN) {
    int i = blockIdx.x * blockDim.x + threadIdx.x;
    if (i < nN) { g_deg[i] = 0; g_cnt[i] = 0; }
}

__global__ void build_edges_kernel(const void* __restrict__ ei, int E, int Etot, int nN) {
    int i = blockIdx.x * blockDim.x + threadIdx.x;
    if (i >= Etot) return;
    int s, d;
    if (i < E) {
        if (g_is64) {
            const long long* p = (const long long*)ei;
            s = (int)p[i]; d = (int)p[E + i];
        } else {
            const int* p = (const int*)ei;
            s = p[i]; d = p[E + i];
        }
        s = min(max(s, 0), nN - 1);
        d = min(max(d, 0), nN - 1);
    } else {
        s = d = i - E;                 // self loops appended
    }
    g_src[i] = s;
    g_dst[i] = d;
    atomicAdd(&g_deg[d], 1);
}

// ---------------- multi-block exclusive scan: g_deg -> g_rowptr ------------
__global__ void scan_partial_kernel(int nN) {
    int b = blockIdx.x, tid = threadIdx.x;
    int base = b * SCAN_CHUNK + tid * 4;
    int s = 0;
#pragma unroll
    for (int j = 0; j < 4; j++) { int i = base + j; if (i < nN) s += g_deg[i]; }
#pragma unroll
    for (int off = 16; off; off >>= 1) s += __shfl_xor_sync(0xffffffffu, s, off);
    __shared__ int ws[8];
    if ((tid & 31) == 0) ws[tid >> 5] = s;
    __syncthreads();
    if (tid == 0) {
        int t = 0;
#pragma unroll
        for (int w = 0; w < 8; w++) t += ws[w];
        g_bsum[b] = t;
    }
}

__global__ void scan_bsums_kernel(int NB) {
    __shared__ int sh[SCAN_NB_MAX];
    int tid = threadIdx.x;
    sh[tid] = (tid < NB) ? g_bsum[tid] : 0;
    __syncthreads();
    for (int off = 1; off < SCAN_NB_MAX; off <<= 1) {
        int v = (tid >= off) ? sh[tid - off] : 0;
        __syncthreads();
        sh[tid] += v;
        __syncthreads();
    }
    g_boff[tid] = tid ? sh[tid - 1] : 0;
}

__global__ void scan_write_kernel(int nN, int Etot) {
    int b = blockIdx.x, tid = threadIdx.x;
    int base = b * SCAN_CHUNK + tid * 4;
    int v[4]; int s = 0;
#pragma unroll
    for (int j = 0; j < 4; j++) {
        int i = base + j;
        v[j] = (i < nN) ? g_deg[i] : 0;
        s += v[j];
    }
    int lane = tid & 31, w = tid >> 5;
    int incl = s;
#pragma unroll
    for (int off = 1; off < 32; off <<= 1) {
        int t = __shfl_up_sync(0xffffffffu, incl, off);
        if (lane >= off) incl += t;
    }
    __shared__ int ws[8], wso[8];
    if (lane == 31) ws[w] = incl;
    __syncthreads();
    if (w == 0 && lane < 8) {
        int x = ws[lane];
        int ix = x;
#pragma unroll
        for (int off = 1; off < 8; off <<= 1) {
            int t = __shfl_up_sync(0xffu, ix, off);
            if (lane >= off) ix += t;
        }
        wso[lane] = ix - x;
    }
    __syncthreads();
    int excl = incl - s + wso[w] + g_boff[b];
#pragma unroll
    for (int j = 0; j < 4; j++) {
        int i = base + j;
        if (i < nN) { g_rowptr[i] = excl; excl += v[j]; }
    }
    if (b == 0 && tid == 0) g_rowptr[nN] = Etot;
}

__global__ void scatter_kernel(int Etot) {
    int i = blockIdx.x * blockDim.x + threadIdx.x;
    if (i >= Etot) return;
    int d   = g_dst[i];
    int pos = g_rowptr[d] + atomicAdd(&g_cnt[d], 1);
    g_csr[pos] = g_src[i];
}

// ---------------- per-layer: h = act(in) @ W ; alpha_s/alpha_d ------------
template <int K, int O, bool PRE>
__global__ void gemm_alpha_kernel(const float* __restrict__ in,
                                  const float* __restrict__ W,
                                  const float* __restrict__ avs,
                                  const float* __restrict__ avd,
                                  const float* __restrict__ pbias,
                                  int nN) {
    constexpr int BN  = 256 / O;           // nodes per block
    constexpr int WPN = O / 32;            // warps per node
    __shared__ float Wsh[K * O];
    __shared__ float insh[BN * K];
    __shared__ float as_sh[O], ad_sh[O];
    __shared__ float ps_sh[8], pd_sh[8];

    int tid = threadIdx.x;
    for (int i = tid; i < K * O; i += 256) Wsh[i] = W[i];
    if (tid < O) { as_sh[tid] = avs[tid]; ad_sh[tid] = avd[tid]; }

    int base = blockIdx.x * BN;
    const float* src = PRE ? g_agg : in;
    for (int i = tid; i < BN * K; i += 256) {
        int nl = i / K, k = i % K;
        int n  = base + nl;
        float v = 0.f;
        if (n < nN) {
            v = src[n * K + k];
            if (PRE) v = fmaxf(v + pbias[k], 0.f);
        }
        insh[i] = v;
    }
    __syncthreads();

    int nl = tid / O, c = tid % O;
    float acc = 0.f;
#pragma unroll
    for (int k = 0; k < K; k++) acc += insh[nl * K + k] * Wsh[k * O + c];

    int n = base + nl;
    if (n < nN) g_h[n * O + c] = acc;

    float ps = acc * as_sh[c];
    float pd = acc * ad_sh[c];
#pragma unroll
    for (int off = 16; off; off >>= 1) {
        ps += __shfl_xor_sync(0xffffffffu, ps, off);
        pd += __shfl_xor_sync(0xffffffffu, pd, off);
    }
    int warpId = tid >> 5;
    if ((tid & 31) == 0) { ps_sh[warpId] = ps; pd_sh[warpId] = pd; }
    __syncthreads();
    if (tid < BN && base + tid < nN) {
        float s = 0.f, d = 0.f;
#pragma unroll
        for (int w = 0; w < WPN; w++) {
            s += ps_sh[tid * WPN + w];
            d += pd_sh[tid * WPN + w];
        }
        g_as[base + tid] = s;
        g_ad[base + tid] = d;
    }
}

// ---------------- per-layer: single-pass online softmax + aggregate -------
// warp per destination node; flash-attention style running (m, sum, acc).
template <int O>
__global__ void aggregate_kernel(int nN) {
    int node = (blockIdx.x * blockDim.x + threadIdx.x) >> 5;
    int lane = threadIdx.x & 31;
    if (node >= nN) return;

    int start = g_rowptr[node];
    int end   = g_rowptr[node + 1];
    float ad  = g_ad[node];

    float m = -1e30f, sum = 0.f;
    float2 acc = make_float2(0.f, 0.f);

    // software prefetch of (src, alpha_src)
    int   s  = g_csr[start];
    float as = g_as[s];

    for (int e = start; e < end; e++) {
        int   e2  = (e + 1 < end) ? (e + 1) : e;
        int   sn  = g_csr[e2];
        float asn = g_as[sn];

        float l = as + ad;
        l = l > 0.f ? l : l * 0.2f;
        float nm    = fmaxf(m, l);
        float scale = __expf(m - nm);          // 0 on first edge (m=-1e30)
        float p     = __expf(l - nm);
        sum = sum * scale + p;

        if (O == 32) {
            float hv = g_h[s * 32 + lane];
            acc.x = acc.x * scale + p * hv;
        } else {
            float2 hv = *reinterpret_cast<const float2*>(&g_h[s * 64 + lane * 2]);
            acc.x = acc.x * scale + p * hv.x;
            acc.y = acc.y * scale + p * hv.y;
        }
        m = nm; s = sn; as = asn;
    }

    float inv = 1.f / (sum + 1e-16f);
    if (O == 32) {
        g_agg[node * 32 + lane] = acc.x * inv;
    } else {
        float2 o = make_float2(acc.x * inv, acc.y * inv);
        *reinterpret_cast<float2*>(&g_agg[node * 64 + lane * 2]) = o;
    }
}

// ---------------- final: out = relu(g_agg + b3) @ Wl + bl -----------------
// Block: 32 nodes x 128 channels; thread: 2 rows x 8 channels via FFMA2.
__global__ void final_gemm_kernel(const float* __restrict__ b3,
                                  const float* __restrict__ Wl,
                                  const float* __restrict__ bl,
                                  float* __restrict__ out, int nN) {
    __shared__ __align__(16) float Wsh[64 * 128];   // 32 KB
    __shared__ __align__(16) float hsh[32 * 65];    // padded rows: no bank conflict

    int tid   = threadIdx.x;
    int cbase = blockIdx.y * 128;
    int nbase = blockIdx.x * 32;

    for (int i = tid; i < 64 * 128; i += 256) {
        int k = i >> 7, c = i & 127;
        Wsh[i] = Wl[k * 512 + cbase + c];
    }
    for (int i = tid; i < 32 * 64; i += 256) {
        int r = i >> 6, k = i & 63;
        int n = nbase + r;
        float v = 0.f;
        if (n < nN) v = fmaxf(g_agg[n * 64 + k] + b3[k], 0.f);
        hsh[r * 65 + k] = v;
    }
    __syncthreads();

    int cidx = tid & 15;    // channel group of 8: channels cidx*8 .. cidx*8+7
    int ridx = tid >> 4;    // 0..15; rows ridx and ridx+16

    unsigned long long acc[2][4];
#pragma unroll
    for (int r = 0; r < 2; r++)
#pragma unroll
        for (int j = 0; j < 4; j++) acc[r][j] = 0ull;

#pragma unroll 8
    for (int k = 0; k < 64; k++) {
        ulonglong2 w0 = *reinterpret_cast<const ulonglong2*>(&Wsh[k * 128 + cidx * 8]);
        ulonglong2 w1 = *reinterpret_cast<const ulonglong2*>(&Wsh[k * 128 + cidx * 8 + 4]);
        float h0 = hsh[ridx * 65 + k];
        float h1 = hsh[(ridx + 16) * 65 + k];
        unsigned long long hh0 = pack2(h0, h0);
        unsigned long long hh1 = pack2(h1, h1);
        ffma2(acc[0][0], hh0, w0.x);
        ffma2(acc[0][1], hh0, w0.y);
        ffma2(acc[0][2], hh0, w1.x);
        ffma2(acc[0][3], hh0, w1.y);
        ffma2(acc[1][0], hh1, w0.x);
        ffma2(acc[1][1], hh1, w0.y);
        ffma2(acc[1][2], hh1, w1.x);
        ffma2(acc[1][3], hh1, w1.y);
    }

    float bl0 = bl[cbase + cidx * 8 + 0];
    float bl1 = bl[cbase + cidx * 8 + 1];
    float bl2 = bl[cbase + cidx * 8 + 2];
    float bl3 = bl[cbase + cidx * 8 + 3];
    float bl4 = bl[cbase + cidx * 8 + 4];
    float bl5 = bl[cbase + cidx * 8 + 5];
    float bl6 = bl[cbase + cidx * 8 + 6];
    float bl7 = bl[cbase + cidx * 8 + 7];

#pragma unroll
    for (int r = 0; r < 2; r++) {
        int n = nbase + ridx + r * 16;
        if (n < nN) {
            float a0, a1, a2, a3, a4, a5, a6, a7;
            unpack2(a0, a1, acc[r][0]);
            unpack2(a2, a3, acc[r][1]);
            unpack2(a4, a5, acc[r][2]);
            unpack2(a6, a7, acc[r][3]);
            float4 o0 = make_float4(a0 + bl0, a1 + bl1, a2 + bl2, a3 + bl3);
            float4 o1 = make_float4(a4 + bl4, a5 + bl5, a6 + bl6, a7 + bl7);
            *reinterpret_cast<float4*>(&out[n * 512 + cbase + cidx * 8])     = o0;
            *reinterpret_cast<float4*>(&out[n * 512 + cbase + cidx * 8 + 4]) = o1;
        }
    }
}

// ---------------- launch ----------------------------------------------------
extern "C" void kernel_launch(void* const* d_in, const int* in_sizes, int n_in,
                              void* d_out, int out_size) {
    const float* x   = (const float*)d_in[0];
    const void*  ei  = d_in[1];
    // d_in[2] = edge_attr: unused by GATConv (edge_dim=None)
    const float* W1 = (const float*)d_in[3];
    const float* as1 = (const float*)d_in[4];
    const float* ad1 = (const float*)d_in[5];
    const float* b1 = (const float*)d_in[6];
    const float* W2 = (const float*)d_in[7];
    const float* as2 = (const float*)d_in[8];
    const float* ad2 = (const float*)d_in[9];
    const float* b2 = (const float*)d_in[10];
    const float* W3 = (const float*)d_in[11];
    const float* as3 = (const float*)d_in[12];
    const float* ad3 = (const float*)d_in[13];
    const float* b3 = (const float*)d_in[14];
    const float* Wl = (const float*)d_in[15];
    const float* bl = (const float*)d_in[16];
    float* out = (float*)d_out;

    int nN   = in_sizes[0] / 128;      // 100000
    int E    = in_sizes[1] / 2;        // 1600000
    int Etot = E + nN;                 // 1700000
    int NB   = (nN + SCAN_CHUNK - 1) / SCAN_CHUNK;   // 98

    // ---- CSR build (once per launch, reused by all 3 layers) ----
    detect_kernel<<<1, 32>>>((const int*)ei);
    zero_counts_kernel<<<(nN + 255) / 256, 256>>>(nN);
    build_edges_kernel<<<(Etot + 255) / 256, 256>>>(ei, E, Etot, nN);
    scan_partial_kernel<<<NB, 256>>>(nN);
    scan_bsums_kernel<<<1, SCAN_NB_MAX>>>(NB);
    scan_write_kernel<<<NB, 256>>>(nN, Etot);
    scatter_kernel<<<(Etot + 255) / 256, 256>>>(Etot);

    int aggBlocks = (nN * 32 + 255) / 256;

    // ---- layer 1: 128 -> 32 ----
    gemm_alpha_kernel<128, 32, false><<<(nN + 7) / 8, 256>>>(x, W1, as1, ad1, nullptr, nN);
    aggregate_kernel<32><<<aggBlocks, 256>>>(nN);

    // ---- layer 2: 32 -> 64 (input = relu(agg1 + b1)) ----
    gemm_alpha_kernel<32, 64, true><<<(nN + 3) / 4, 256>>>(nullptr, W2, as2, ad2, b1, nN);
    aggregate_kernel<64><<<aggBlocks, 256>>>(nN);

    // ---- layer 3: 64 -> 64 (input = relu(agg2 + b2)) ----
    gemm_alpha_kernel<64, 64, true><<<(nN + 3) / 4, 256>>>(nullptr, W3, as3, ad3, b2, nN);
    aggregate_kernel<64><<<aggBlocks, 256>>>(nN);

    // ---- final linear: relu(agg3 + b3) @ Wl + bl ----
    dim3 fgrid((nN + 31) / 32, 4);
    final_gemm_kernel<<<fgrid, 256>>>(b3, Wl, bl, out, nN);
}

// round 5
// speedup vs baseline: 1.3802x; 1.3802x over previous
#include <cuda_runtime.h>
#include <math.h>

#define NMAX   100000
#define ETOTMX 1700000
#define SCAN_CHUNK 1024
#define SCAN_NB_MAX 128

// ---------------- scratch (static device globals; no allocation) ----------
__device__ int   g_is64;
__device__ int   g_src[ETOTMX];
__device__ int   g_dst[ETOTMX];
__device__ int   g_csr[ETOTMX];
__device__ int   g_deg[NMAX];
__device__ int   g_cnt[NMAX];
__device__ int   g_rowptr[NMAX + 1];
__device__ int   g_bsum[SCAN_NB_MAX];
__device__ int   g_boff[SCAN_NB_MAX];
__device__ __align__(16) float g_h[NMAX * 64];
__device__ __align__(16) float g_agg[NMAX * 64];
__device__ float g_as[NMAX];
__device__ float g_ad[NMAX];

// ---------------- dtype sniff: int64 vs int32 edge_index -------------------
__global__ void detect_kernel(const int* __restrict__ ei32) {
    if (threadIdx.x == 0) {
        int ok = 1;
        for (int i = 0; i < 256; i++)
            if (ei32[2 * i + 1] != 0) { ok = 0; break; }
        g_is64 = ok;
    }
}

// ---------------- graph build ---------------------------------------------
__global__ void zero_counts_kernel(int nN) {
    int i = blockIdx.x * blockDim.x + threadIdx.x;
    if (i < nN) { g_deg[i] = 0; g_cnt[i] = 0; }
}

__global__ void build_edges_kernel(const void* __restrict__ ei, int E, int Etot, int nN) {
    int i = blockIdx.x * blockDim.x + threadIdx.x;
    if (i >= Etot) return;
    int s, d;
    if (i < E) {
        if (g_is64) {
            const long long* p = (const long long*)ei;
            s = (int)p[i]; d = (int)p[E + i];
        } else {
            const int* p = (const int*)ei;
            s = p[i]; d = p[E + i];
        }
        s = min(max(s, 0), nN - 1);
        d = min(max(d, 0), nN - 1);
    } else {
        s = d = i - E;                 // self loops appended
    }
    g_src[i] = s;
    g_dst[i] = d;
    atomicAdd(&g_deg[d], 1);
}

// ---------------- multi-block exclusive scan: g_deg -> g_rowptr ------------
__global__ void scan_partial_kernel(int nN) {
    int b = blockIdx.x, tid = threadIdx.x;
    int base = b * SCAN_CHUNK + tid * 4;
    int s = 0;
#pragma unroll
    for (int j = 0; j < 4; j++) { int i = base + j; if (i < nN) s += g_deg[i]; }
#pragma unroll
    for (int off = 16; off; off >>= 1) s += __shfl_xor_sync(0xffffffffu, s, off);
    __shared__ int ws[8];
    if ((tid & 31) == 0) ws[tid >> 5] = s;
    __syncthreads();
    if (tid == 0) {
        int t = 0;
#pragma unroll
        for (int w = 0; w < 8; w++) t += ws[w];
        g_bsum[b] = t;
    }
}

__global__ void scan_bsums_kernel(int NB) {
    __shared__ int sh[SCAN_NB_MAX];
    int tid = threadIdx.x;
    sh[tid] = (tid < NB) ? g_bsum[tid] : 0;
    __syncthreads();
    for (int off = 1; off < SCAN_NB_MAX; off <<= 1) {
        int v = (tid >= off) ? sh[tid - off] : 0;
        __syncthreads();
        sh[tid] += v;
        __syncthreads();
    }
    g_boff[tid] = tid ? sh[tid - 1] : 0;
}

__global__ void scan_write_kernel(int nN, int Etot) {
    int b = blockIdx.x, tid = threadIdx.x;
    int base = b * SCAN_CHUNK + tid * 4;
    int v[4]; int s = 0;
#pragma unroll
    for (int j = 0; j < 4; j++) {
        int i = base + j;
        v[j] = (i < nN) ? g_deg[i] : 0;
        s += v[j];
    }
    int lane = tid & 31, w = tid >> 5;
    int incl = s;
#pragma unroll
    for (int off = 1; off < 32; off <<= 1) {
        int t = __shfl_up_sync(0xffffffffu, incl, off);
        if (lane >= off) incl += t;
    }
    __shared__ int ws[8], wso[8];
    if (lane == 31) ws[w] = incl;
    __syncthreads();
    if (w == 0 && lane < 8) {
        int x = ws[lane];
        int ix = x;
#pragma unroll
        for (int off = 1; off < 8; off <<= 1) {
            int t = __shfl_up_sync(0xffu, ix, off);
            if (lane >= off) ix += t;
        }
        wso[lane] = ix - x;
    }
    __syncthreads();
    int excl = incl - s + wso[w] + g_boff[b];
#pragma unroll
    for (int j = 0; j < 4; j++) {
        int i = base + j;
        if (i < nN) { g_rowptr[i] = excl; excl += v[j]; }
    }
    if (b == 0 && tid == 0) g_rowptr[nN] = Etot;
}

__global__ void scatter_kernel(int Etot) {
    int i = blockIdx.x * blockDim.x + threadIdx.x;
    if (i >= Etot) return;
    int d   = g_dst[i];
    int pos = g_rowptr[d] + atomicAdd(&g_cnt[d], 1);
    g_csr[pos] = g_src[i];
}

// ---------------- per-layer: h = act(in) @ W ; alpha_s/alpha_d ------------
template <int K, int O, bool PRE>
__global__ void gemm_alpha_kernel(const float* __restrict__ in,
                                  const float* __restrict__ W,
                                  const float* __restrict__ avs,
                                  const float* __restrict__ avd,
                                  const float* __restrict__ pbias,
                                  int nN) {
    constexpr int BN  = 256 / O;           // nodes per block
    constexpr int WPN = O / 32;            // warps per node
    __shared__ float Wsh[K * O];
    __shared__ float insh[BN * K];
    __shared__ float as_sh[O], ad_sh[O];
    __shared__ float ps_sh[8], pd_sh[8];

    int tid = threadIdx.x;
    for (int i = tid; i < K * O; i += 256) Wsh[i] = W[i];
    if (tid < O) { as_sh[tid] = avs[tid]; ad_sh[tid] = avd[tid]; }

    int base = blockIdx.x * BN;
    const float* src = PRE ? g_agg : in;
    for (int i = tid; i < BN * K; i += 256) {
        int nl = i / K, k = i % K;
        int n  = base + nl;
        float v = 0.f;
        if (n < nN) {
            v = src[n * K + k];
            if (PRE) v = fmaxf(v + pbias[k], 0.f);
        }
        insh[i] = v;
    }
    __syncthreads();

    int nl = tid / O, c = tid % O;
    float acc = 0.f;
#pragma unroll
    for (int k = 0; k < K; k++) acc += insh[nl * K + k] * Wsh[k * O + c];

    int n = base + nl;
    if (n < nN) g_h[n * O + c] = acc;

    float ps = acc * as_sh[c];
    float pd = acc * ad_sh[c];
#pragma unroll
    for (int off = 16; off; off >>= 1) {
        ps += __shfl_xor_sync(0xffffffffu, ps, off);
        pd += __shfl_xor_sync(0xffffffffu, pd, off);
    }
    int warpId = tid >> 5;
    if ((tid & 31) == 0) { ps_sh[warpId] = ps; pd_sh[warpId] = pd; }
    __syncthreads();
    if (tid < BN && base + tid < nN) {
        float s = 0.f, d = 0.f;
#pragma unroll
        for (int w = 0; w < WPN; w++) {
            s += ps_sh[tid * WPN + w];
            d += pd_sh[tid * WPN + w];
        }
        g_as[base + tid] = s;
        g_ad[base + tid] = d;
    }
}

// ---------------- per-layer: softmax + weighted aggregate (warp/node) -----
// 3-pass: strided max, strided exp-sum, gather (unroll-4, MLP=4).
template <int O>
__global__ void aggregate_kernel(int nN) {
    int node = (blockIdx.x * blockDim.x + threadIdx.x) >> 5;
    int lane = threadIdx.x & 31;
    if (node >= nN) return;

    int start = g_rowptr[node];
    int end   = g_rowptr[node + 1];
    float ad  = g_ad[node];

    // pass 1: segment max (lane-strided)
    float m = -1e30f;
    for (int e = start + lane; e < end; e += 32) {
        int s = g_csr[e];
        float l = g_as[s] + ad;
        l = l > 0.f ? l : l * 0.2f;
        m = fmaxf(m, l);
    }
#pragma unroll
    for (int off = 16; off; off >>= 1) m = fmaxf(m, __shfl_xor_sync(0xffffffffu, m, off));

    // pass 2: segment exp-sum (lane-strided)
    float sum = 0.f;
    for (int e = start + lane; e < end; e += 32) {
        int s = g_csr[e];
        float l = g_as[s] + ad;
        l = l > 0.f ? l : l * 0.2f;
        sum += __expf(l - m);
    }
#pragma unroll
    for (int off = 16; off; off >>= 1) sum += __shfl_xor_sync(0xffffffffu, sum, off);
    float inv = 1.f / (sum + 1e-16f);

    // pass 3: weighted gather, unrolled x4 with independent accumulators
    if (O == 32) {
        float a0 = 0.f, a1 = 0.f, a2 = 0.f, a3 = 0.f;
        int e = start;
        for (; e + 4 <= end; e += 4) {
            int s0 = g_csr[e], s1 = g_csr[e + 1], s2 = g_csr[e + 2], s3 = g_csr[e + 3];
            float l0 = g_as[s0] + ad, l1 = g_as[s1] + ad;
            float l2 = g_as[s2] + ad, l3 = g_as[s3] + ad;
            l0 = l0 > 0.f ? l0 : l0 * 0.2f;
            l1 = l1 > 0.f ? l1 : l1 * 0.2f;
            l2 = l2 > 0.f ? l2 : l2 * 0.2f;
            l3 = l3 > 0.f ? l3 : l3 * 0.2f;
            float w0 = __expf(l0 - m), w1 = __expf(l1 - m);
            float w2 = __expf(l2 - m), w3 = __expf(l3 - m);
            a0 += w0 * g_h[s0 * 32 + lane];
            a1 += w1 * g_h[s1 * 32 + lane];
            a2 += w2 * g_h[s2 * 32 + lane];
            a3 += w3 * g_h[s3 * 32 + lane];
        }
        for (; e < end; e++) {
            int s = g_csr[e];
            float l = g_as[s] + ad;
            l = l > 0.f ? l : l * 0.2f;
            a0 += __expf(l - m) * g_h[s * 32 + lane];
        }
        g_agg[node * 32 + lane] = ((a0 + a1) + (a2 + a3)) * inv;
    } else {
        float2 a0 = make_float2(0.f, 0.f), a1 = make_float2(0.f, 0.f);
        float2 a2 = make_float2(0.f, 0.f), a3 = make_float2(0.f, 0.f);
        int e = start;
        for (; e + 4 <= end; e += 4) {
            int s0 = g_csr[e], s1 = g_csr[e + 1], s2 = g_csr[e + 2], s3 = g_csr[e + 3];
            float l0 = g_as[s0] + ad, l1 = g_as[s1] + ad;
            float l2 = g_as[s2] + ad, l3 = g_as[s3] + ad;
            l0 = l0 > 0.f ? l0 : l0 * 0.2f;
            l1 = l1 > 0.f ? l1 : l1 * 0.2f;
            l2 = l2 > 0.f ? l2 : l2 * 0.2f;
            l3 = l3 > 0.f ? l3 : l3 * 0.2f;
            float w0 = __expf(l0 - m), w1 = __expf(l1 - m);
            float w2 = __expf(l2 - m), w3 = __expf(l3 - m);
            float2 h0 = *reinterpret_cast<const float2*>(&g_h[s0 * 64 + lane * 2]);
            float2 h1 = *reinterpret_cast<const float2*>(&g_h[s1 * 64 + lane * 2]);
            float2 h2 = *reinterpret_cast<const float2*>(&g_h[s2 * 64 + lane * 2]);
            float2 h3 = *reinterpret_cast<const float2*>(&g_h[s3 * 64 + lane * 2]);
            a0.x += w0 * h0.x; a0.y += w0 * h0.y;
            a1.x += w1 * h1.x; a1.y += w1 * h1.y;
            a2.x += w2 * h2.x; a2.y += w2 * h2.y;
            a3.x += w3 * h3.x; a3.y += w3 * h3.y;
        }
        for (; e < end; e++) {
            int s = g_csr[e];
            float l = g_as[s] + ad;
            l = l > 0.f ? l : l * 0.2f;
            float w = __expf(l - m);
            float2 hv = *reinterpret_cast<const float2*>(&g_h[s * 64 + lane * 2]);
            a0.x += w * hv.x; a0.y += w * hv.y;
        }
        float2 o;
        o.x = ((a0.x + a1.x) + (a2.x + a3.x)) * inv;
        o.y = ((a0.y + a1.y) + (a2.y + a3.y)) * inv;
        *reinterpret_cast<float2*>(&g_agg[node * 64 + lane * 2]) = o;
    }
}

// ---------------- final: out = relu(g_agg + b3) @ Wl + bl -----------------
// Each block: 32 nodes x 128 output channels. Static shared only (~40.5KB).
__global__ void final_gemm_kernel(const float* __restrict__ b3,
                                  const float* __restrict__ Wl,
                                  const float* __restrict__ bl,
                                  float* __restrict__ out, int nN) {
    __shared__ __align__(16) float Wsh[64 * 128];   // 32 KB
    __shared__ __align__(16) float hsh[32 * 64];    // 8 KB
    __shared__ float blsh[128];

    int tid    = threadIdx.x;
    int cbase  = blockIdx.y * 128;      // channel split base
    int nbase  = blockIdx.x * 32;       // node tile base

    for (int i = tid; i < 64 * 128; i += 256) {
        int k = i >> 7, c = i & 127;
        Wsh[i] = Wl[k * 512 + cbase + c];
    }
    if (tid < 128) blsh[tid] = bl[cbase + tid];

    for (int i = tid; i < 32 * 64; i += 256) {
        int n = nbase + (i >> 6);
        int k = i & 63;
        float v = 0.f;
        if (n < nN) v = fmaxf(g_agg[n * 64 + k] + b3[k], 0.f);
        hsh[i] = v;
    }
    __syncthreads();

    int cidx = tid & 31;    // channel group of 4
    int ridx = tid >> 5;    // 0..7; rows ridx, ridx+8, ridx+16, ridx+24

    float acc[4][4];
#pragma unroll
    for (int r = 0; r < 4; r++)
#pragma unroll
        for (int j = 0; j < 4; j++) acc[r][j] = 0.f;

#pragma unroll 8
    for (int k = 0; k < 64; k++) {
        float4 w = *reinterpret_cast<const float4*>(&Wsh[k * 128 + cidx * 4]);
#pragma unroll
        for (int r = 0; r < 4; r++) {
            float hv = hsh[(ridx + r * 8) * 64 + k];
            acc[r][0] += hv * w.x;
            acc[r][1] += hv * w.y;
            acc[r][2] += hv * w.z;
            acc[r][3] += hv * w.w;
        }
    }

#pragma unroll
    for (int r = 0; r < 4; r++) {
        int n = nbase + ridx + r * 8;
        if (n < nN) {
            float4 o;
            o.x = acc[r][0] + blsh[cidx * 4 + 0];
            o.y = acc[r][1] + blsh[cidx * 4 + 1];
            o.z = acc[r][2] + blsh[cidx * 4 + 2];
            o.w = acc[r][3] + blsh[cidx * 4 + 3];
            *reinterpret_cast<float4*>(&out[n * 512 + cbase + cidx * 4]) = o;
        }
    }
}

// ---------------- launch ----------------------------------------------------
extern "C" void kernel_launch(void* const* d_in, const int* in_sizes, int n_in,
                              void* d_out, int out_size) {
    const float* x   = (const float*)d_in[0];
    const void*  ei  = d_in[1];
    // d_in[2] = edge_attr: unused by GATConv (edge_dim=None)
    const float* W1 = (const float*)d_in[3];
    const float* as1 = (const float*)d_in[4];
    const float* ad1 = (const float*)d_in[5];
    const float* b1 = (const float*)d_in[6];
    const float* W2 = (const float*)d_in[7];
    const float* as2 = (const float*)d_in[8];
    const float* ad2 = (const float*)d_in[9];
    const float* b2 = (const float*)d_in[10];
    const float* W3 = (const float*)d_in[11];
    const float* as3 = (const float*)d_in[12];
    const float* ad3 = (const float*)d_in[13];
    const float* b3 = (const float*)d_in[14];
    const float* Wl = (const float*)d_in[15];
    const float* bl = (const float*)d_in[16];
    float* out = (float*)d_out;

    int nN   = in_sizes[0] / 128;      // 100000
    int E    = in_sizes[1] / 2;        // 1600000
    int Etot = E + nN;                 // 1700000
    int NB   = (nN + SCAN_CHUNK - 1) / SCAN_CHUNK;   // 98

    // ---- CSR build (once per launch, reused by all 3 layers) ----
    detect_kernel<<<1, 32>>>((const int*)ei);
    zero_counts_kernel<<<(nN + 255) / 256, 256>>>(nN);
    build_edges_kernel<<<(Etot + 255) / 256, 256>>>(ei, E, Etot, nN);
    scan_partial_kernel<<<NB, 256>>>(nN);
    scan_bsums_kernel<<<1, SCAN_NB_MAX>>>(NB);
    scan_write_kernel<<<NB, 256>>>(nN, Etot);
    scatter_kernel<<<(Etot + 255) / 256, 256>>>(Etot);

    int aggBlocks = (nN * 32 + 255) / 256;

    // ---- layer 1: 128 -> 32 ----
    gemm_alpha_kernel<128, 32, false><<<(nN + 7) / 8, 256>>>(x, W1, as1, ad1, nullptr, nN);
    aggregate_kernel<32><<<aggBlocks, 256>>>(nN);

    // ---- layer 2: 32 -> 64 (input = relu(agg1 + b1)) ----
    gemm_alpha_kernel<32, 64, true><<<(nN + 3) / 4, 256>>>(nullptr, W2, as2, ad2, b1, nN);
    aggregate_kernel<64><<<aggBlocks, 256>>>(nN);

    // ---- layer 3: 64 -> 64 (input = relu(agg2 + b2)) ----
    gemm_alpha_kernel<64, 64, true><<<(nN + 3) / 4, 256>>>(nullptr, W3, as3, ad3, b2, nN);
    aggregate_kernel<64><<<aggBlocks, 256>>>(nN);

    // ---- final linear: relu(agg3 + b3) @ Wl + bl ----
    dim3 fgrid((nN + 31) / 32, 4);
    final_gemm_kernel<<<fgrid, 256>>>(b3, Wl, bl, out, nN);
}

// round 6
// speedup vs baseline: 1.5686x; 1.1365x over previous
#include <cuda_runtime.h>
#include <math.h>

#define NMAX   100000
#define ETOTMX 1700000
#define SCAN_CHUNK 1024
#define SCAN_NB_MAX 128

// ---------------- scratch (static device globals; no allocation) ----------
__device__ int   g_is64;
__device__ int   g_src[ETOTMX];
__device__ int   g_dst[ETOTMX];
__device__ int   g_csr[ETOTMX];
__device__ int   g_deg[NMAX];
__device__ int   g_cnt[NMAX];
__device__ int   g_rowptr[NMAX + 1];
__device__ int   g_bsum[SCAN_NB_MAX];
__device__ int   g_boff[SCAN_NB_MAX];
__device__ __align__(16) float g_h[NMAX * 64];
__device__ __align__(16) float g_agg[NMAX * 64];
__device__ float g_as[NMAX];
__device__ float g_ad[NMAX];

// ---------------- dtype sniff: int64 vs int32 edge_index -------------------
__global__ void detect_kernel(const int* __restrict__ ei32) {
    if (threadIdx.x == 0) {
        int ok = 1;
        for (int i = 0; i < 256; i++)
            if (ei32[2 * i + 1] != 0) { ok = 0; break; }
        g_is64 = ok;
    }
}

// ---------------- graph build ---------------------------------------------
__global__ void zero_counts_kernel(int nN) {
    int i = blockIdx.x * blockDim.x + threadIdx.x;
    if (i < nN) { g_deg[i] = 0; g_cnt[i] = 0; }
}

__global__ void build_edges_kernel(const void* __restrict__ ei, int E, int Etot, int nN) {
    int i = blockIdx.x * blockDim.x + threadIdx.x;
    if (i >= Etot) return;
    int s, d;
    if (i < E) {
        if (g_is64) {
            const long long* p = (const long long*)ei;
            s = (int)p[i]; d = (int)p[E + i];
        } else {
            const int* p = (const int*)ei;
            s = p[i]; d = p[E + i];
        }
        s = min(max(s, 0), nN - 1);
        d = min(max(d, 0), nN - 1);
    } else {
        s = d = i - E;                 // self loops appended
    }
    g_src[i] = s;
    g_dst[i] = d;
    atomicAdd(&g_deg[d], 1);
}

// ---------------- multi-block exclusive scan: g_deg -> g_rowptr ------------
__global__ void scan_partial_kernel(int nN) {
    int b = blockIdx.x, tid = threadIdx.x;
    int base = b * SCAN_CHUNK + tid * 4;
    int s = 0;
#pragma unroll
    for (int j = 0; j < 4; j++) { int i = base + j; if (i < nN) s += g_deg[i]; }
#pragma unroll
    for (int off = 16; off; off >>= 1) s += __shfl_xor_sync(0xffffffffu, s, off);
    __shared__ int ws[8];
    if ((tid & 31) == 0) ws[tid >> 5] = s;
    __syncthreads();
    if (tid == 0) {
        int t = 0;
#pragma unroll
        for (int w = 0; w < 8; w++) t += ws[w];
        g_bsum[b] = t;
    }
}

__global__ void scan_bsums_kernel(int NB) {
    __shared__ int sh[SCAN_NB_MAX];
    int tid = threadIdx.x;
    sh[tid] = (tid < NB) ? g_bsum[tid] : 0;
    __syncthreads();
    for (int off = 1; off < SCAN_NB_MAX; off <<= 1) {
        int v = (tid >= off) ? sh[tid - off] : 0;
        __syncthreads();
        sh[tid] += v;
        __syncthreads();
    }
    g_boff[tid] = tid ? sh[tid - 1] : 0;
}

__global__ void scan_write_kernel(int nN, int Etot) {
    int b = blockIdx.x, tid = threadIdx.x;
    int base = b * SCAN_CHUNK + tid * 4;
    int v[4]; int s = 0;
#pragma unroll
    for (int j = 0; j < 4; j++) {
        int i = base + j;
        v[j] = (i < nN) ? g_deg[i] : 0;
        s += v[j];
    }
    int lane = tid & 31, w = tid >> 5;
    int incl = s;
#pragma unroll
    for (int off = 1; off < 32; off <<= 1) {
        int t = __shfl_up_sync(0xffffffffu, incl, off);
        if (lane >= off) incl += t;
    }
    __shared__ int ws[8], wso[8];
    if (lane == 31) ws[w] = incl;
    __syncthreads();
    if (w == 0 && lane < 8) {
        int x = ws[lane];
        int ix = x;
#pragma unroll
        for (int off = 1; off < 8; off <<= 1) {
            int t = __shfl_up_sync(0xffu, ix, off);
            if (lane >= off) ix += t;
        }
        wso[lane] = ix - x;
    }
    __syncthreads();
    int excl = incl - s + wso[w] + g_boff[b];
#pragma unroll
    for (int j = 0; j < 4; j++) {
        int i = base + j;
        if (i < nN) { g_rowptr[i] = excl; excl += v[j]; }
    }
    if (b == 0 && tid == 0) g_rowptr[nN] = Etot;
}

__global__ void scatter_kernel(int Etot) {
    int i = blockIdx.x * blockDim.x + threadIdx.x;
    if (i >= Etot) return;
    int d   = g_dst[i];
    int pos = g_rowptr[d] + atomicAdd(&g_cnt[d], 1);
    g_csr[pos] = g_src[i];
}

// ---------------- per-layer: h = act(in) @ W ; alpha_s/alpha_d ------------
// Register-tiled: thread = 1 node x 4 channels (float4 W loads).
template <int K, int O, bool PRE>
__global__ void gemm_alpha_kernel(const float* __restrict__ in,
                                  const float* __restrict__ W,
                                  const float* __restrict__ avs,
                                  const float* __restrict__ avd,
                                  const float* __restrict__ pbias,
                                  int nN) {
    constexpr int TPN = O / 4;             // threads per node
    constexpr int BN  = 256 / TPN;         // nodes per block
    constexpr int KP  = K + 1;             // padded row (bank-conflict free)
    __shared__ __align__(16) float Wsh[K * O];
    __shared__ float insh[BN * KP];
    __shared__ float as_sh[O], ad_sh[O];

    int tid = threadIdx.x;
    for (int i = tid; i < K * O; i += 256) Wsh[i] = W[i];
    if (tid < O) { as_sh[tid] = avs[tid]; ad_sh[tid] = avd[tid]; }

    int base = blockIdx.x * BN;
    const float* src = PRE ? g_agg : in;
    for (int i = tid; i < BN * K; i += 256) {
        int nl = i / K, k = i % K;
        int n  = base + nl;
        float v = 0.f;
        if (n < nN) {
            v = src[n * K + k];
            if (PRE) v = fmaxf(v + pbias[k], 0.f);
        }
        insh[nl * KP + k] = v;
    }
    __syncthreads();

    int nl = tid / TPN, ci = tid % TPN;
    int n  = base + nl;

    float4 acc = make_float4(0.f, 0.f, 0.f, 0.f);
#pragma unroll
    for (int k = 0; k < K; k++) {
        float hv = insh[nl * KP + k];
        float4 w = *reinterpret_cast<const float4*>(&Wsh[k * O + ci * 4]);
        acc.x += hv * w.x;
        acc.y += hv * w.y;
        acc.z += hv * w.z;
        acc.w += hv * w.w;
    }

    if (n < nN)
        *reinterpret_cast<float4*>(&g_h[n * O + ci * 4]) = acc;

    float4 a_s = *reinterpret_cast<const float4*>(&as_sh[ci * 4]);
    float4 a_d = *reinterpret_cast<const float4*>(&ad_sh[ci * 4]);
    float ps = acc.x * a_s.x + acc.y * a_s.y + acc.z * a_s.z + acc.w * a_s.w;
    float pd = acc.x * a_d.x + acc.y * a_d.y + acc.z * a_d.z + acc.w * a_d.w;
#pragma unroll
    for (int off = TPN / 2; off; off >>= 1) {
        ps += __shfl_down_sync(0xffffffffu, ps, off);
        pd += __shfl_down_sync(0xffffffffu, pd, off);
    }
    if (ci == 0 && n < nN) {
        g_as[n] = ps;
        g_ad[n] = pd;
    }
}

// ---------------- per-layer: single-pass softmax + aggregate (warp/node) ---
// Logits are bounded (|l| << 80), so exp without max-shift is safe; the
// denominator is accumulated in the same pass (lane-replicated, free).
// Unroll-4 with independent accumulators keeps gather MLP=4.
template <int O>
__global__ void aggregate_kernel(int nN) {
    int node = (blockIdx.x * blockDim.x + threadIdx.x) >> 5;
    int lane = threadIdx.x & 31;
    if (node >= nN) return;

    int start = g_rowptr[node];
    int end   = g_rowptr[node + 1];
    float ad  = g_ad[node];

    float sum0 = 0.f, sum1 = 0.f, sum2 = 0.f, sum3 = 0.f;

    if (O == 32) {
        float a0 = 0.f, a1 = 0.f, a2 = 0.f, a3 = 0.f;
        int e = start;
        for (; e + 4 <= end; e += 4) {
            int s0 = g_csr[e], s1 = g_csr[e + 1], s2 = g_csr[e + 2], s3 = g_csr[e + 3];
            float l0 = g_as[s0] + ad, l1 = g_as[s1] + ad;
            float l2 = g_as[s2] + ad, l3 = g_as[s3] + ad;
            l0 = l0 > 0.f ? l0 : l0 * 0.2f;
            l1 = l1 > 0.f ? l1 : l1 * 0.2f;
            l2 = l2 > 0.f ? l2 : l2 * 0.2f;
            l3 = l3 > 0.f ? l3 : l3 * 0.2f;
            float w0 = __expf(l0), w1 = __expf(l1);
            float w2 = __expf(l2), w3 = __expf(l3);
            sum0 += w0; sum1 += w1; sum2 += w2; sum3 += w3;
            a0 += w0 * g_h[s0 * 32 + lane];
            a1 += w1 * g_h[s1 * 32 + lane];
            a2 += w2 * g_h[s2 * 32 + lane];
            a3 += w3 * g_h[s3 * 32 + lane];
        }
        for (; e < end; e++) {
            int s = g_csr[e];
            float l = g_as[s] + ad;
            l = l > 0.f ? l : l * 0.2f;
            float w = __expf(l);
            sum0 += w;
            a0 += w * g_h[s * 32 + lane];
        }
        float sum = (sum0 + sum1) + (sum2 + sum3);
        float inv = 1.f / (sum + 1e-16f);
        g_agg[node * 32 + lane] = ((a0 + a1) + (a2 + a3)) * inv;
    } else {
        float2 a0 = make_float2(0.f, 0.f), a1 = make_float2(0.f, 0.f);
        float2 a2 = make_float2(0.f, 0.f), a3 = make_float2(0.f, 0.f);
        int e = start;
        for (; e + 4 <= end; e += 4) {
            int s0 = g_csr[e], s1 = g_csr[e + 1], s2 = g_csr[e + 2], s3 = g_csr[e + 3];
            float l0 = g_as[s0] + ad, l1 = g_as[s1] + ad;
            float l2 = g_as[s2] + ad, l3 = g_as[s3] + ad;
            l0 = l0 > 0.f ? l0 : l0 * 0.2f;
            l1 = l1 > 0.f ? l1 : l1 * 0.2f;
            l2 = l2 > 0.f ? l2 : l2 * 0.2f;
            l3 = l3 > 0.f ? l3 : l3 * 0.2f;
            float w0 = __expf(l0), w1 = __expf(l1);
            float w2 = __expf(l2), w3 = __expf(l3);
            sum0 += w0; sum1 += w1; sum2 += w2; sum3 += w3;
            float2 h0 = *reinterpret_cast<const float2*>(&g_h[s0 * 64 + lane * 2]);
            float2 h1 = *reinterpret_cast<const float2*>(&g_h[s1 * 64 + lane * 2]);
            float2 h2 = *reinterpret_cast<const float2*>(&g_h[s2 * 64 + lane * 2]);
            float2 h3 = *reinterpret_cast<const float2*>(&g_h[s3 * 64 + lane * 2]);
            a0.x += w0 * h0.x; a0.y += w0 * h0.y;
            a1.x += w1 * h1.x; a1.y += w1 * h1.y;
            a2.x += w2 * h2.x; a2.y += w2 * h2.y;
            a3.x += w3 * h3.x; a3.y += w3 * h3.y;
        }
        for (; e < end; e++) {
            int s = g_csr[e];
            float l = g_as[s] + ad;
            l = l > 0.f ? l : l * 0.2f;
            float w = __expf(l);
            sum0 += w;
            float2 hv = *reinterpret_cast<const float2*>(&g_h[s * 64 + lane * 2]);
            a0.x += w * hv.x; a0.y += w * hv.y;
        }
        float sum = (sum0 + sum1) + (sum2 + sum3);
        float inv = 1.f / (sum + 1e-16f);
        float2 o;
        o.x = ((a0.x + a1.x) + (a2.x + a3.x)) * inv;
        o.y = ((a0.y + a1.y) + (a2.y + a3.y)) * inv;
        *reinterpret_cast<float2*>(&g_agg[node * 64 + lane * 2]) = o;
    }
}

// ---------------- final: out = relu(g_agg + b3) @ Wl + bl -----------------
// Each block: 32 nodes x 128 output channels. Static shared only (~40.5KB).
__global__ void final_gemm_kernel(const float* __restrict__ b3,
                                  const float* __restrict__ Wl,
                                  const float* __restrict__ bl,
                                  float* __restrict__ out, int nN) {
    __shared__ __align__(16) float Wsh[64 * 128];   // 32 KB
    __shared__ __align__(16) float hsh[32 * 64];    // 8 KB
    __shared__ float blsh[128];

    int tid    = threadIdx.x;
    int cbase  = blockIdx.y * 128;      // channel split base
    int nbase  = blockIdx.x * 32;       // node tile base

    for (int i = tid; i < 64 * 128; i += 256) {
        int k = i >> 7, c = i & 127;
        Wsh[i] = Wl[k * 512 + cbase + c];
    }
    if (tid < 128) blsh[tid] = bl[cbase + tid];

    for (int i = tid; i < 32 * 64; i += 256) {
        int n = nbase + (i >> 6);
        int k = i & 63;
        float v = 0.f;
        if (n < nN) v = fmaxf(g_agg[n * 64 + k] + b3[k], 0.f);
        hsh[i] = v;
    }
    __syncthreads();

    int cidx = tid & 31;    // channel group of 4
    int ridx = tid >> 5;    // 0..7; rows ridx, ridx+8, ridx+16, ridx+24

    float acc[4][4];
#pragma unroll
    for (int r = 0; r < 4; r++)
#pragma unroll
        for (int j = 0; j < 4; j++) acc[r][j] = 0.f;

#pragma unroll 8
    for (int k = 0; k < 64; k++) {
        float4 w = *reinterpret_cast<const float4*>(&Wsh[k * 128 + cidx * 4]);
#pragma unroll
        for (int r = 0; r < 4; r++) {
            float hv = hsh[(ridx + r * 8) * 64 + k];
            acc[r][0] += hv * w.x;
            acc[r][1] += hv * w.y;
            acc[r][2] += hv * w.z;
            acc[r][3] += hv * w.w;
        }
    }

#pragma unroll
    for (int r = 0; r < 4; r++) {
        int n = nbase + ridx + r * 8;
        if (n < nN) {
            float4 o;
            o.x = acc[r][0] + blsh[cidx * 4 + 0];
            o.y = acc[r][1] + blsh[cidx * 4 + 1];
            o.z = acc[r][2] + blsh[cidx * 4 + 2];
            o.w = acc[r][3] + blsh[cidx * 4 + 3];
            *reinterpret_cast<float4*>(&out[n * 512 + cbase + cidx * 4]) = o;
        }
    }
}

// ---------------- launch ----------------------------------------------------
extern "C" void kernel_launch(void* const* d_in, const int* in_sizes, int n_in,
                              void* d_out, int out_size) {
    const float* x   = (const float*)d_in[0];
    const void*  ei  = d_in[1];
    // d_in[2] = edge_attr: unused by GATConv (edge_dim=None)
    const float* W1 = (const float*)d_in[3];
    const float* as1 = (const float*)d_in[4];
    const float* ad1 = (const float*)d_in[5];
    const float* b1 = (const float*)d_in[6];
    const float* W2 = (const float*)d_in[7];
    const float* as2 = (const float*)d_in[8];
    const float* ad2 = (const float*)d_in[9];
    const float* b2 = (const float*)d_in[10];
    const float* W3 = (const float*)d_in[11];
    const float* as3 = (const float*)d_in[12];
    const float* ad3 = (const float*)d_in[13];
    const float* b3 = (const float*)d_in[14];
    const float* Wl = (const float*)d_in[15];
    const float* bl = (const float*)d_in[16];
    float* out = (float*)d_out;

    int nN   = in_sizes[0] / 128;      // 100000
    int E    = in_sizes[1] / 2;        // 1600000
    int Etot = E + nN;                 // 1700000
    int NB   = (nN + SCAN_CHUNK - 1) / SCAN_CHUNK;   // 98

    // ---- CSR build (once per launch, reused by all 3 layers) ----
    detect_kernel<<<1, 32>>>((const int*)ei);
    zero_counts_kernel<<<(nN + 255) / 256, 256>>>(nN);
    build_edges_kernel<<<(Etot + 255) / 256, 256>>>(ei, E, Etot, nN);
    scan_partial_kernel<<<NB, 256>>>(nN);
    scan_bsums_kernel<<<1, SCAN_NB_MAX>>>(NB);
    scan_write_kernel<<<NB, 256>>>(nN, Etot);
    scatter_kernel<<<(Etot + 255) / 256, 256>>>(Etot);

    int aggBlocks = (nN * 32 + 255) / 256;

    // ---- layer 1: 128 -> 32 ----  (TPN=8, BN=32)
    gemm_alpha_kernel<128, 32, false><<<(nN + 31) / 32, 256>>>(x, W1, as1, ad1, nullptr, nN);
    aggregate_kernel<32><<<aggBlocks, 256>>>(nN);

    // ---- layer 2: 32 -> 64 (input = relu(agg1 + b1)) ----  (TPN=16, BN=16)
    gemm_alpha_kernel<32, 64, true><<<(nN + 15) / 16, 256>>>(nullptr, W2, as2, ad2, b1, nN);
    aggregate_kernel<64><<<aggBlocks, 256>>>(nN);

    // ---- layer 3: 64 -> 64 (input = relu(agg2 + b2)) ----
    gemm_alpha_kernel<64, 64, true><<<(nN + 15) / 16, 256>>>(nullptr, W3, as3, ad3, b2, nN);
    aggregate_kernel<64><<<aggBlocks, 256>>>(nN);

    // ---- final linear: relu(agg3 + b3) @ Wl + bl ----
    dim3 fgrid((nN + 31) / 32, 4);
    final_gemm_kernel<<<fgrid, 256>>>(b3, Wl, bl, out, nN);
}

// round 7
// speedup vs baseline: 1.7930x; 1.1430x over previous
#include <cuda_runtime.h>
#include <cuda_bf16.h>
#include <math.h>

#define NMAX   100000
#define ETOTMX 1700000
#define SCAN_CHUNK 1024
#define SCAN_NB_MAX 128

// ---------------- scratch (static device globals; no allocation) ----------
__device__ int   g_is64;
__device__ int   g_src[ETOTMX];
__device__ int   g_dst[ETOTMX];
__device__ int   g_csr[ETOTMX];
__device__ int   g_deg[NMAX];
__device__ int   g_cnt[NMAX];
__device__ int   g_rowptr[NMAX + 1];
__device__ int   g_bsum[SCAN_NB_MAX];
__device__ int   g_boff[SCAN_NB_MAX];
__device__ __align__(16) float g_h[NMAX * 64];
__device__ __align__(16) float g_agg[NMAX * 64];
__device__ float g_as[NMAX];
__device__ float g_ad[NMAX];

// ---------------- dtype sniff: int64 vs int32 edge_index -------------------
__global__ void detect_kernel(const int* __restrict__ ei32) {
    if (threadIdx.x == 0) {
        int ok = 1;
        for (int i = 0; i < 256; i++)
            if (ei32[2 * i + 1] != 0) { ok = 0; break; }
        g_is64 = ok;
    }
}

// ---------------- graph build ---------------------------------------------
__global__ void zero_counts_kernel(int nN) {
    int i = blockIdx.x * blockDim.x + threadIdx.x;
    if (i < nN) { g_deg[i] = 0; g_cnt[i] = 0; }
}

__global__ void build_edges_kernel(const void* __restrict__ ei, int E, int Etot, int nN) {
    int i = blockIdx.x * blockDim.x + threadIdx.x;
    if (i >= Etot) return;
    int s, d;
    if (i < E) {
        if (g_is64) {
            const long long* p = (const long long*)ei;
            s = (int)p[i]; d = (int)p[E + i];
        } else {
            const int* p = (const int*)ei;
            s = p[i]; d = p[E + i];
        }
        s = min(max(s, 0), nN - 1);
        d = min(max(d, 0), nN - 1);
    } else {
        s = d = i - E;                 // self loops appended
    }
    g_src[i] = s;
    g_dst[i] = d;
    atomicAdd(&g_deg[d], 1);
}

// ---------------- multi-block exclusive scan: g_deg -> g_rowptr ------------
__global__ void scan_partial_kernel(int nN) {
    int b = blockIdx.x, tid = threadIdx.x;
    int base = b * SCAN_CHUNK + tid * 4;
    int s = 0;
#pragma unroll
    for (int j = 0; j < 4; j++) { int i = base + j; if (i < nN) s += g_deg[i]; }
#pragma unroll
    for (int off = 16; off; off >>= 1) s += __shfl_xor_sync(0xffffffffu, s, off);
    __shared__ int ws[8];
    if ((tid & 31) == 0) ws[tid >> 5] = s;
    __syncthreads();
    if (tid == 0) {
        int t = 0;
#pragma unroll
        for (int w = 0; w < 8; w++) t += ws[w];
        g_bsum[b] = t;
    }
}

__global__ void scan_bsums_kernel(int NB) {
    __shared__ int sh[SCAN_NB_MAX];
    int tid = threadIdx.x;
    sh[tid] = (tid < NB) ? g_bsum[tid] : 0;
    __syncthreads();
    for (int off = 1; off < SCAN_NB_MAX; off <<= 1) {
        int v = (tid >= off) ? sh[tid - off] : 0;
        __syncthreads();
        sh[tid] += v;
        __syncthreads();
    }
    g_boff[tid] = tid ? sh[tid - 1] : 0;
}

__global__ void scan_write_kernel(int nN, int Etot) {
    int b = blockIdx.x, tid = threadIdx.x;
    int base = b * SCAN_CHUNK + tid * 4;
    int v[4]; int s = 0;
#pragma unroll
    for (int j = 0; j < 4; j++) {
        int i = base + j;
        v[j] = (i < nN) ? g_deg[i] : 0;
        s += v[j];
    }
    int lane = tid & 31, w = tid >> 5;
    int incl = s;
#pragma unroll
    for (int off = 1; off < 32; off <<= 1) {
        int t = __shfl_up_sync(0xffffffffu, incl, off);
        if (lane >= off) incl += t;
    }
    __shared__ int ws[8], wso[8];
    if (lane == 31) ws[w] = incl;
    __syncthreads();
    if (w == 0 && lane < 8) {
        int x = ws[lane];
        int ix = x;
#pragma unroll
        for (int off = 1; off < 8; off <<= 1) {
            int t = __shfl_up_sync(0xffu, ix, off);
            if (lane >= off) ix += t;
        }
        wso[lane] = ix - x;
    }
    __syncthreads();
    int excl = incl - s + wso[w] + g_boff[b];
#pragma unroll
    for (int j = 0; j < 4; j++) {
        int i = base + j;
        if (i < nN) { g_rowptr[i] = excl; excl += v[j]; }
    }
    if (b == 0 && tid == 0) g_rowptr[nN] = Etot;
}

__global__ void scatter_kernel(int Etot) {
    int i = blockIdx.x * blockDim.x + threadIdx.x;
    if (i >= Etot) return;
    int d   = g_dst[i];
    int pos = g_rowptr[d] + atomicAdd(&g_cnt[d], 1);
    g_csr[pos] = g_src[i];
}

// ---------------- per-layer: h = act(in) @ W ; alpha_s/alpha_d ------------
// Register-tiled: thread = 1 node x 4 channels (float4 W loads).
template <int K, int O, bool PRE>
__global__ void gemm_alpha_kernel(const float* __restrict__ in,
                                  const float* __restrict__ W,
                                  const float* __restrict__ avs,
                                  const float* __restrict__ avd,
                                  const float* __restrict__ pbias,
                                  int nN) {
    constexpr int TPN = O / 4;             // threads per node
    constexpr int BN  = 256 / TPN;         // nodes per block
    constexpr int KP  = K + 1;             // padded row (bank-conflict free)
    __shared__ __align__(16) float Wsh[K * O];
    __shared__ float insh[BN * KP];
    __shared__ float as_sh[O], ad_sh[O];

    int tid = threadIdx.x;
    for (int i = tid; i < K * O; i += 256) Wsh[i] = W[i];
    if (tid < O) { as_sh[tid] = avs[tid]; ad_sh[tid] = avd[tid]; }

    int base = blockIdx.x * BN;
    const float* src = PRE ? g_agg : in;
    for (int i = tid; i < BN * K; i += 256) {
        int nl = i / K, k = i % K;
        int n  = base + nl;
        float v = 0.f;
        if (n < nN) {
            v = src[n * K + k];
            if (PRE) v = fmaxf(v + pbias[k], 0.f);
        }
        insh[nl * KP + k] = v;
    }
    __syncthreads();

    int nl = tid / TPN, ci = tid % TPN;
    int n  = base + nl;

    float4 acc = make_float4(0.f, 0.f, 0.f, 0.f);
#pragma unroll
    for (int k = 0; k < K; k++) {
        float hv = insh[nl * KP + k];
        float4 w = *reinterpret_cast<const float4*>(&Wsh[k * O + ci * 4]);
        acc.x += hv * w.x;
        acc.y += hv * w.y;
        acc.z += hv * w.z;
        acc.w += hv * w.w;
    }

    if (n < nN)
        *reinterpret_cast<float4*>(&g_h[n * O + ci * 4]) = acc;

    float4 a_s = *reinterpret_cast<const float4*>(&as_sh[ci * 4]);
    float4 a_d = *reinterpret_cast<const float4*>(&ad_sh[ci * 4]);
    float ps = acc.x * a_s.x + acc.y * a_s.y + acc.z * a_s.z + acc.w * a_s.w;
    float pd = acc.x * a_d.x + acc.y * a_d.y + acc.z * a_d.z + acc.w * a_d.w;
#pragma unroll
    for (int off = TPN / 2; off; off >>= 1) {
        ps += __shfl_down_sync(0xffffffffu, ps, off);
        pd += __shfl_down_sync(0xffffffffu, pd, off);
    }
    if (ci == 0 && n < nN) {
        g_as[n] = ps;
        g_ad[n] = pd;
    }
}

// ---------------- per-layer: single-pass softmax + aggregate (warp/node) ---
template <int O>
__global__ void aggregate_kernel(int nN) {
    int node = (blockIdx.x * blockDim.x + threadIdx.x) >> 5;
    int lane = threadIdx.x & 31;
    if (node >= nN) return;

    int start = g_rowptr[node];
    int end   = g_rowptr[node + 1];
    float ad  = g_ad[node];

    float sum0 = 0.f, sum1 = 0.f, sum2 = 0.f, sum3 = 0.f;

    if (O == 32) {
        float a0 = 0.f, a1 = 0.f, a2 = 0.f, a3 = 0.f;
        int e = start;
        for (; e + 4 <= end; e += 4) {
            int s0 = g_csr[e], s1 = g_csr[e + 1], s2 = g_csr[e + 2], s3 = g_csr[e + 3];
            float l0 = g_as[s0] + ad, l1 = g_as[s1] + ad;
            float l2 = g_as[s2] + ad, l3 = g_as[s3] + ad;
            l0 = l0 > 0.f ? l0 : l0 * 0.2f;
            l1 = l1 > 0.f ? l1 : l1 * 0.2f;
            l2 = l2 > 0.f ? l2 : l2 * 0.2f;
            l3 = l3 > 0.f ? l3 : l3 * 0.2f;
            float w0 = __expf(l0), w1 = __expf(l1);
            float w2 = __expf(l2), w3 = __expf(l3);
            sum0 += w0; sum1 += w1; sum2 += w2; sum3 += w3;
            a0 += w0 * g_h[s0 * 32 + lane];
            a1 += w1 * g_h[s1 * 32 + lane];
            a2 += w2 * g_h[s2 * 32 + lane];
            a3 += w3 * g_h[s3 * 32 + lane];
        }
        for (; e < end; e++) {
            int s = g_csr[e];
            float l = g_as[s] + ad;
            l = l > 0.f ? l : l * 0.2f;
            float w = __expf(l);
            sum0 += w;
            a0 += w * g_h[s * 32 + lane];
        }
        float sum = (sum0 + sum1) + (sum2 + sum3);
        float inv = 1.f / (sum + 1e-16f);
        g_agg[node * 32 + lane] = ((a0 + a1) + (a2 + a3)) * inv;
    } else {
        float2 a0 = make_float2(0.f, 0.f), a1 = make_float2(0.f, 0.f);
        float2 a2 = make_float2(0.f, 0.f), a3 = make_float2(0.f, 0.f);
        int e = start;
        for (; e + 4 <= end; e += 4) {
            int s0 = g_csr[e], s1 = g_csr[e + 1], s2 = g_csr[e + 2], s3 = g_csr[e + 3];
            float l0 = g_as[s0] + ad, l1 = g_as[s1] + ad;
            float l2 = g_as[s2] + ad, l3 = g_as[s3] + ad;
            l0 = l0 > 0.f ? l0 : l0 * 0.2f;
            l1 = l1 > 0.f ? l1 : l1 * 0.2f;
            l2 = l2 > 0.f ? l2 : l2 * 0.2f;
            l3 = l3 > 0.f ? l3 : l3 * 0.2f;
            float w0 = __expf(l0), w1 = __expf(l1);
            float w2 = __expf(l2), w3 = __expf(l3);
            sum0 += w0; sum1 += w1; sum2 += w2; sum3 += w3;
            float2 h0 = *reinterpret_cast<const float2*>(&g_h[s0 * 64 + lane * 2]);
            float2 h1 = *reinterpret_cast<const float2*>(&g_h[s1 * 64 + lane * 2]);
            float2 h2 = *reinterpret_cast<const float2*>(&g_h[s2 * 64 + lane * 2]);
            float2 h3 = *reinterpret_cast<const float2*>(&g_h[s3 * 64 + lane * 2]);
            a0.x += w0 * h0.x; a0.y += w0 * h0.y;
            a1.x += w1 * h1.x; a1.y += w1 * h1.y;
            a2.x += w2 * h2.x; a2.y += w2 * h2.y;
            a3.x += w3 * h3.x; a3.y += w3 * h3.y;
        }
        for (; e < end; e++) {
            int s = g_csr[e];
            float l = g_as[s] + ad;
            l = l > 0.f ? l : l * 0.2f;
            float w = __expf(l);
            sum0 += w;
            float2 hv = *reinterpret_cast<const float2*>(&g_h[s * 64 + lane * 2]);
            a0.x += w * hv.x; a0.y += w * hv.y;
        }
        float sum = (sum0 + sum1) + (sum2 + sum3);
        float inv = 1.f / (sum + 1e-16f);
        float2 o;
        o.x = ((a0.x + a1.x) + (a2.x + a3.x)) * inv;
        o.y = ((a0.y + a1.y) + (a2.y + a3.y)) * inv;
        *reinterpret_cast<float2*>(&g_agg[node * 64 + lane * 2]) = o;
    }
}

// ---------------- final GEMM: tensor cores (mma.sync bf16, split hi/lo) ----
// out = relu(g_agg + b3) @ Wl + bl, computed as (ahi+alo)(bhi+blo) minus lo*lo.
// CTA: 128 nodes x 128 channels, K=64. 8 warps, warp = 16-row band.
#define FG_PAD 72   // row stride in elements: (4g+t) mod 32 -> conflict-free

__device__ __forceinline__ void mma_bf16(float& d0, float& d1, float& d2, float& d3,
                                         unsigned a0, unsigned a1, unsigned a2, unsigned a3,
                                         unsigned b0, unsigned b1) {
    asm volatile(
        "mma.sync.aligned.m16n8k16.row.col.f32.bf16.bf16.f32 "
        "{%0,%1,%2,%3}, {%4,%5,%6,%7}, {%8,%9}, {%0,%1,%2,%3};"
        : "+f"(d0), "+f"(d1), "+f"(d2), "+f"(d3)
        : "r"(a0), "r"(a1), "r"(a2), "r"(a3), "r"(b0), "r"(b1));
}

__global__ void __launch_bounds__(256)
final_gemm_mma_kernel(const float* __restrict__ b3,
                      const float* __restrict__ Wl,
                      const float* __restrict__ bl,
                      float* __restrict__ out, int nN) {
    extern __shared__ __align__(16) char smem_raw[];
    __nv_bfloat16* Ahi = reinterpret_cast<__nv_bfloat16*>(smem_raw);
    __nv_bfloat16* Alo = Ahi + 128 * FG_PAD;
    __nv_bfloat16* Bhi = Alo + 128 * FG_PAD;   // stored transposed: [chan][k]
    __nv_bfloat16* Blo = Bhi + 128 * FG_PAD;
    __shared__ float blsh[128];

    int tid   = threadIdx.x;
    int cbase = blockIdx.y * 128;
    int nbase = blockIdx.x * 128;

    if (tid < 128) blsh[tid] = bl[cbase + tid];

    // stage A = relu(g_agg + b3) split into bf16 hi/lo
    for (int i = tid; i < 128 * 64; i += 256) {
        int r = i >> 6, k = i & 63;
        int n = nbase + r;
        float v = 0.f;
        if (n < nN) v = fmaxf(g_agg[n * 64 + k] + b3[k], 0.f);
        __nv_bfloat16 hi = __float2bfloat16_rn(v);
        __nv_bfloat16 lo = __float2bfloat16_rn(v - __bfloat162float(hi));
        Ahi[r * FG_PAD + k] = hi;
        Alo[r * FG_PAD + k] = lo;
    }
    // stage B^T = Wl[k][cbase+c] -> Bhi/Blo[c][k]
    for (int i = tid; i < 64 * 128; i += 256) {
        int k = i >> 7, c = i & 127;
        float w = Wl[k * 512 + cbase + c];
        __nv_bfloat16 hi = __float2bfloat16_rn(w);
        __nv_bfloat16 lo = __float2bfloat16_rn(w - __bfloat162float(hi));
        Bhi[c * FG_PAD + k] = hi;
        Blo[c * FG_PAD + k] = lo;
    }
    __syncthreads();

    int warp = tid >> 5;
    int lane = tid & 31;
    int g    = lane >> 2;       // group id (0..7)
    int t    = lane & 3;        // thread in group
    int R    = warp * 16;       // row band

    float d[16][4];
#pragma unroll
    for (int nt = 0; nt < 16; nt++)
#pragma unroll
        for (int j = 0; j < 4; j++) d[nt][j] = 0.f;

#pragma unroll
    for (int kk = 0; kk < 64; kk += 16) {
        // A fragments (hi & lo) for this warp's 16-row band
        const __nv_bfloat16* ah = &Ahi[(R + g) * FG_PAD + kk + t * 2];
        const __nv_bfloat16* al = &Alo[(R + g) * FG_PAD + kk + t * 2];
        unsigned ah0 = *reinterpret_cast<const unsigned*>(ah);
        unsigned ah1 = *reinterpret_cast<const unsigned*>(ah + 8 * FG_PAD);
        unsigned ah2 = *reinterpret_cast<const unsigned*>(ah + 8);
        unsigned ah3 = *reinterpret_cast<const unsigned*>(ah + 8 * FG_PAD + 8);
        unsigned al0 = *reinterpret_cast<const unsigned*>(al);
        unsigned al1 = *reinterpret_cast<const unsigned*>(al + 8 * FG_PAD);
        unsigned al2 = *reinterpret_cast<const unsigned*>(al + 8);
        unsigned al3 = *reinterpret_cast<const unsigned*>(al + 8 * FG_PAD + 8);

#pragma unroll
        for (int nt = 0; nt < 16; nt++) {
            const __nv_bfloat16* bh = &Bhi[(nt * 8 + g) * FG_PAD + kk + t * 2];
            const __nv_bfloat16* blp = &Blo[(nt * 8 + g) * FG_PAD + kk + t * 2];
            unsigned bh0 = *reinterpret_cast<const unsigned*>(bh);
            unsigned bh1 = *reinterpret_cast<const unsigned*>(bh + 8);
            unsigned bl0 = *reinterpret_cast<const unsigned*>(blp);
            unsigned bl1 = *reinterpret_cast<const unsigned*>(blp + 8);
            mma_bf16(d[nt][0], d[nt][1], d[nt][2], d[nt][3],
                     ah0, ah1, ah2, ah3, bh0, bh1);
            mma_bf16(d[nt][0], d[nt][1], d[nt][2], d[nt][3],
                     ah0, ah1, ah2, ah3, bl0, bl1);
            mma_bf16(d[nt][0], d[nt][1], d[nt][2], d[nt][3],
                     al0, al1, al2, al3, bh0, bh1);
        }
    }

    // epilogue: d[nt] -> rows (R+g, R+g+8), cols nt*8 + t*2 + {0,1}
    int n0 = nbase + R + g;
    int n1 = n0 + 8;
#pragma unroll
    for (int nt = 0; nt < 16; nt++) {
        int c = nt * 8 + t * 2;
        float b0 = blsh[c], b1 = blsh[c + 1];
        if (n0 < nN) {
            float2 o = make_float2(d[nt][0] + b0, d[nt][1] + b1);
            *reinterpret_cast<float2*>(&out[n0 * 512 + cbase + c]) = o;
        }
        if (n1 < nN) {
            float2 o = make_float2(d[nt][2] + b0, d[nt][3] + b1);
            *reinterpret_cast<float2*>(&out[n1 * 512 + cbase + c]) = o;
        }
    }
}

// ---------------- launch ----------------------------------------------------
extern "C" void kernel_launch(void* const* d_in, const int* in_sizes, int n_in,
                              void* d_out, int out_size) {
    const float* x   = (const float*)d_in[0];
    const void*  ei  = d_in[1];
    // d_in[2] = edge_attr: unused by GATConv (edge_dim=None)
    const float* W1 = (const float*)d_in[3];
    const float* as1 = (const float*)d_in[4];
    const float* ad1 = (const float*)d_in[5];
    const float* b1 = (const float*)d_in[6];
    const float* W2 = (const float*)d_in[7];
    const float* as2 = (const float*)d_in[8];
    const float* ad2 = (const float*)d_in[9];
    const float* b2 = (const float*)d_in[10];
    const float* W3 = (const float*)d_in[11];
    const float* as3 = (const float*)d_in[12];
    const float* ad3 = (const float*)d_in[13];
    const float* b3 = (const float*)d_in[14];
    const float* Wl = (const float*)d_in[15];
    const float* bl = (const float*)d_in[16];
    float* out = (float*)d_out;

    int nN   = in_sizes[0] / 128;      // 100000
    int E    = in_sizes[1] / 2;        // 1600000
    int Etot = E + nN;                 // 1700000
    int NB   = (nN + SCAN_CHUNK - 1) / SCAN_CHUNK;   // 98

    // ---- CSR build (once per launch, reused by all 3 layers) ----
    detect_kernel<<<1, 32>>>((const int*)ei);
    zero_counts_kernel<<<(nN + 255) / 256, 256>>>(nN);
    build_edges_kernel<<<(Etot + 255) / 256, 256>>>(ei, E, Etot, nN);
    scan_partial_kernel<<<NB, 256>>>(nN);
    scan_bsums_kernel<<<1, SCAN_NB_MAX>>>(NB);
    scan_write_kernel<<<NB, 256>>>(nN, Etot);
    scatter_kernel<<<(Etot + 255) / 256, 256>>>(Etot);

    int aggBlocks = (nN * 32 + 255) / 256;

    // ---- layer 1: 128 -> 32 ----
    gemm_alpha_kernel<128, 32, false><<<(nN + 31) / 32, 256>>>(x, W1, as1, ad1, nullptr, nN);
    aggregate_kernel<32><<<aggBlocks, 256>>>(nN);

    // ---- layer 2: 32 -> 64 ----
    gemm_alpha_kernel<32, 64, true><<<(nN + 15) / 16, 256>>>(nullptr, W2, as2, ad2, b1, nN);
    aggregate_kernel<64><<<aggBlocks, 256>>>(nN);

    // ---- layer 3: 64 -> 64 ----
    gemm_alpha_kernel<64, 64, true><<<(nN + 15) / 16, 256>>>(nullptr, W3, as3, ad3, b2, nN);
    aggregate_kernel<64><<<aggBlocks, 256>>>(nN);

    // ---- final linear on tensor cores ----
    const int FG_SMEM = 4 * 128 * FG_PAD * (int)sizeof(__nv_bfloat16);  // 73728
    cudaFuncSetAttribute(final_gemm_mma_kernel,
                         cudaFuncAttributeMaxDynamicSharedMemorySize, FG_SMEM);
    dim3 fgrid((nN + 127) / 128, 4);
    final_gemm_mma_kernel<<<fgrid, 256, FG_SMEM>>>(b3, Wl, bl, out, nN);
}